// round 1
// baseline (speedup 1.0000x reference)
#include <cuda_runtime.h>
#include <cstdint>

// Problem constants
#define B_  8
#define S_  1024
#define D_  1024
#define H_  16
#define DH_ 64
#define BSD_ (B_ * S_ * D_)                       // 8,388,608
#define SCALE_ 0.125f                             // 1/sqrt(64)

// ---------------------------------------------------------------------------
// Scratch (alloc-free rule: __device__ globals)
// ---------------------------------------------------------------------------
__device__ float g_q[BSD_];
__device__ float g_k[BSD_];
__device__ float g_v[BSD_];
__device__ float g_ctx[BSD_];
__device__ float g_attn[(size_t)B_ * H_ * S_ * S_];   // 536 MB, logits -> softmax in place

// ---------------------------------------------------------------------------
// SGEMM with bias: C[M,N] = A[M,K] @ W[K,N] + bias[N]
// BM=BN=64, BK=16, 256 threads, 4x4 micro-tile per thread
// ---------------------------------------------------------------------------
__global__ __launch_bounds__(256)
void sgemm_bias(const float* __restrict__ A, const float* __restrict__ W,
                const float* __restrict__ bias, float* __restrict__ C,
                int M, int N, int K) {
    __shared__ float As[16][65];   // [k][m], padded (scalar stores)
    __shared__ float Ws[16][64];   // [k][n], float4-aligned rows

    const int t  = threadIdx.x;
    const int tx = t & 15;
    const int ty = t >> 4;
    const int row0 = blockIdx.y * 64;
    const int col0 = blockIdx.x * 64;

    float acc[4][4] = {};

    for (int k0 = 0; k0 < K; k0 += 16) {
        // A tile: 64 rows x 16 k
        {
            int m  = t >> 2;
            int kq = (t & 3) * 4;
            float4 v = *(const float4*)(A + (size_t)(row0 + m) * K + k0 + kq);
            As[kq + 0][m] = v.x; As[kq + 1][m] = v.y;
            As[kq + 2][m] = v.z; As[kq + 3][m] = v.w;
        }
        // W tile: 16 k x 64 n
        {
            int kk = t >> 4;
            int nq = (t & 15) * 4;
            *(float4*)&Ws[kk][nq] =
                *(const float4*)(W + (size_t)(k0 + kk) * N + col0 + nq);
        }
        __syncthreads();

        #pragma unroll
        for (int kk = 0; kk < 16; kk++) {
            float a[4], b[4];
            #pragma unroll
            for (int i = 0; i < 4; i++) a[i] = As[kk][ty * 4 + i];
            #pragma unroll
            for (int j = 0; j < 4; j++) b[j] = Ws[kk][tx * 4 + j];
            #pragma unroll
            for (int i = 0; i < 4; i++)
                #pragma unroll
                for (int j = 0; j < 4; j++)
                    acc[i][j] += a[i] * b[j];
        }
        __syncthreads();
    }

    #pragma unroll
    for (int i = 0; i < 4; i++) {
        int r = row0 + ty * 4 + i;
        #pragma unroll
        for (int j = 0; j < 4; j++) {
            int c = col0 + tx * 4 + j;
            C[(size_t)r * N + c] = acc[i][j] + bias[c];
        }
    }
}

// ---------------------------------------------------------------------------
// logits[b,h,i,j] = scale * dot(Q[b,i,h,:], K[b,j,h,:])   (DH=64, full-K tile)
// 64x64 output tile per block, 256 threads, 4x4 per thread
// ---------------------------------------------------------------------------
__global__ __launch_bounds__(256)
void logits_kernel() {
    const int bh = blockIdx.z;
    const int b  = bh >> 4;
    const int h  = bh & 15;
    const float* Qb = g_q + (size_t)b * S_ * D_ + h * DH_;
    const float* Kb = g_k + (size_t)b * S_ * D_ + h * DH_;
    float* Ob = g_attn + (size_t)bh * S_ * S_;

    __shared__ float Qs[64][68];   // [row][d], pad 68 keeps float4 align + no conflicts
    __shared__ float Ks[64][68];

    const int t  = threadIdx.x;
    const int tx = t & 15;
    const int ty = t >> 4;
    const int i0 = blockIdx.y * 64;
    const int j0 = blockIdx.x * 64;

    #pragma unroll
    for (int r = 0; r < 4; r++) {
        int row = (t >> 4) + r * 16;
        int col = (t & 15) * 4;
        *(float4*)&Qs[row][col] = *(const float4*)(Qb + (size_t)(i0 + row) * D_ + col);
        *(float4*)&Ks[row][col] = *(const float4*)(Kb + (size_t)(j0 + row) * D_ + col);
    }
    __syncthreads();

    float acc[4][4] = {};
    #pragma unroll
    for (int d = 0; d < DH_; d++) {
        float a[4], bb[4];
        #pragma unroll
        for (int i = 0; i < 4; i++) a[i]  = Qs[ty * 4 + i][d];
        #pragma unroll
        for (int j = 0; j < 4; j++) bb[j] = Ks[tx * 4 + j][d];
        #pragma unroll
        for (int i = 0; i < 4; i++)
            #pragma unroll
            for (int j = 0; j < 4; j++)
                acc[i][j] += a[i] * bb[j];
    }

    #pragma unroll
    for (int i = 0; i < 4; i++)
        #pragma unroll
        for (int j = 0; j < 4; j++)
            Ob[(size_t)(i0 + ty * 4 + i) * S_ + j0 + tx * 4 + j] = acc[i][j] * SCALE_;
}

// ---------------------------------------------------------------------------
// Row softmax over S=1024, in place on g_attn; optional duplicate to attn_out
// One block per row, 256 threads x 4 elements
// ---------------------------------------------------------------------------
__global__ __launch_bounds__(256)
void softmax_kernel(float* __restrict__ attn_out) {
    const size_t row = blockIdx.x;
    float* p = g_attn + row * S_;
    const int t = threadIdx.x;

    float v[4];
    float m = -3.402823466e38f;
    #pragma unroll
    for (int i = 0; i < 4; i++) { v[i] = p[t + i * 256]; m = fmaxf(m, v[i]); }

    __shared__ float red[8];
    #pragma unroll
    for (int o = 16; o; o >>= 1) m = fmaxf(m, __shfl_xor_sync(0xffffffffu, m, o));
    if ((t & 31) == 0) red[t >> 5] = m;
    __syncthreads();
    m = red[0];
    #pragma unroll
    for (int w = 1; w < 8; w++) m = fmaxf(m, red[w]);
    __syncthreads();

    float s = 0.f;
    #pragma unroll
    for (int i = 0; i < 4; i++) { v[i] = __expf(v[i] - m); s += v[i]; }
    #pragma unroll
    for (int o = 16; o; o >>= 1) s += __shfl_xor_sync(0xffffffffu, s, o);
    if ((t & 31) == 0) red[t >> 5] = s;
    __syncthreads();
    s = 0.f;
    #pragma unroll
    for (int w = 0; w < 8; w++) s += red[w];

    const float inv = 1.f / s;
    #pragma unroll
    for (int i = 0; i < 4; i++) {
        float r = v[i] * inv;
        p[t + i * 256] = r;
        if (attn_out) attn_out[row * S_ + t + i * 256] = r;
    }
}

// ---------------------------------------------------------------------------
// ctx[b,i,h,:] = attn[b,h,i,:] @ V[b,:,h,:]    M=1024, N=64(full), K=1024
// 64 rows x 64 cols per block, BK=32, 256 threads, 4x4 per thread
// ---------------------------------------------------------------------------
__global__ __launch_bounds__(256)
void ctx_kernel() {
    const int bh = blockIdx.z;
    const int b  = bh >> 4;
    const int h  = bh & 15;
    const float* Pb = g_attn + (size_t)bh * S_ * S_;
    const float* Vb = g_v   + (size_t)b * S_ * D_ + h * DH_;
    float* Ob       = g_ctx + (size_t)b * S_ * D_ + h * DH_;

    __shared__ float Ps[64][33];   // [row][k], padded (scalar stores)
    __shared__ float Vs[32][64];   // [k][d]

    const int t  = threadIdx.x;
    const int tx = t & 15;
    const int ty = t >> 4;
    const int i0 = blockIdx.x * 64;

    float acc[4][4] = {};

    for (int k0 = 0; k0 < S_; k0 += 32) {
        #pragma unroll
        for (int r = 0; r < 2; r++) {
            int m  = (t >> 3) + r * 32;
            int kq = (t & 7) * 4;
            float4 v = *(const float4*)(Pb + (size_t)(i0 + m) * S_ + k0 + kq);
            Ps[m][kq + 0] = v.x; Ps[m][kq + 1] = v.y;
            Ps[m][kq + 2] = v.z; Ps[m][kq + 3] = v.w;
        }
        #pragma unroll
        for (int r = 0; r < 2; r++) {
            int kk = (t >> 4) + r * 16;
            int dq = (t & 15) * 4;
            *(float4*)&Vs[kk][dq] =
                *(const float4*)(Vb + (size_t)(k0 + kk) * D_ + dq);
        }
        __syncthreads();

        #pragma unroll
        for (int kk = 0; kk < 32; kk++) {
            float a[4], bb[4];
            #pragma unroll
            for (int i = 0; i < 4; i++) a[i]  = Ps[ty * 4 + i][kk];
            #pragma unroll
            for (int j = 0; j < 4; j++) bb[j] = Vs[kk][tx * 4 + j];
            #pragma unroll
            for (int i = 0; i < 4; i++)
                #pragma unroll
                for (int j = 0; j < 4; j++)
                    acc[i][j] += a[i] * bb[j];
        }
        __syncthreads();
    }

    #pragma unroll
    for (int i = 0; i < 4; i++)
        #pragma unroll
        for (int j = 0; j < 4; j++)
            Ob[(size_t)(i0 + ty * 4 + i) * D_ + tx * 4 + j] = acc[i][j];
}

// ---------------------------------------------------------------------------
// Launch
// Inputs: 0 query, 1 key, 2 value, 3 Wq, 4 bq, 5 Wk, 6 bk, 7 Wv, 8 bv, 9 Wo, 10 bo
// Output: out [B,S,D]  (+ attn [B,H,S,S] appended if out_size covers it)
// ---------------------------------------------------------------------------
extern "C" void kernel_launch(void* const* d_in, const int* in_sizes, int n_in,
                              void* d_out, int out_size) {
    const float* query = (const float*)d_in[0];
    const float* key   = (const float*)d_in[1];
    const float* value = (const float*)d_in[2];
    const float* Wq    = (const float*)d_in[3];
    const float* bq    = (const float*)d_in[4];
    const float* Wk    = (const float*)d_in[5];
    const float* bk    = (const float*)d_in[6];
    const float* Wv    = (const float*)d_in[7];
    const float* bv    = (const float*)d_in[8];
    const float* Wo    = (const float*)d_in[9];
    const float* bo    = (const float*)d_in[10];
    float* out = (float*)d_out;

    float *q_ptr, *k_ptr, *v_ptr, *ctx_ptr;
    cudaGetSymbolAddress((void**)&q_ptr,   g_q);
    cudaGetSymbolAddress((void**)&k_ptr,   g_k);
    cudaGetSymbolAddress((void**)&v_ptr,   g_v);
    cudaGetSymbolAddress((void**)&ctx_ptr, g_ctx);

    const long long bhss = (long long)B_ * H_ * S_ * S_;
    float* attn_out = nullptr;
    if ((long long)out_size >= (long long)BSD_ + bhss)
        attn_out = out + BSD_;

    dim3 gproj(D_ / 64, (B_ * S_) / 64);            // (16, 128)
    sgemm_bias<<<gproj, 256>>>(query, Wq, bq, q_ptr, B_ * S_, D_, D_);
    sgemm_bias<<<gproj, 256>>>(key,   Wk, bk, k_ptr, B_ * S_, D_, D_);
    sgemm_bias<<<gproj, 256>>>(value, Wv, bv, v_ptr, B_ * S_, D_, D_);

    logits_kernel<<<dim3(S_ / 64, S_ / 64, B_ * H_), 256>>>();
    softmax_kernel<<<B_ * H_ * S_, 256>>>(attn_out);
    ctx_kernel<<<dim3(S_ / 64, 1, B_ * H_), 256>>>();

    sgemm_bias<<<gproj, 256>>>(ctx_ptr, Wo, bo, out, B_ * S_, D_, D_);
}

// round 2
// speedup vs baseline: 1.9384x; 1.9384x over previous
#include <cuda_runtime.h>
#include <cstdint>

// Problem constants
#define B_  8
#define S_  1024
#define D_  1024
#define H_  16
#define DH_ 64
#define BSD_ (B_ * S_ * D_)                       // 8,388,608
#define SCALE_ 0.125f                             // 1/sqrt(64)

// ---------------------------------------------------------------------------
// Scratch (alloc-free rule: __device__ globals)
// ---------------------------------------------------------------------------
__device__ float g_q[BSD_];
__device__ float g_k[BSD_];
__device__ float g_v[BSD_];
__device__ float g_ctx[BSD_];
__device__ float g_attn[(size_t)B_ * H_ * S_ * S_];   // 536 MB, logits -> softmax in place

// ---------------------------------------------------------------------------
// TF32 helpers
// ---------------------------------------------------------------------------
__device__ __forceinline__ float to_tf32(float x) {
    uint32_t u;
    asm("cvt.rna.tf32.f32 %0, %1;" : "=r"(u) : "f"(x));
    return __uint_as_float(u);
}

__device__ __forceinline__ void mma_tf32(float c[4],
                                         const float a[4], const float b[2]) {
    uint32_t a0 = __float_as_uint(a[0]), a1 = __float_as_uint(a[1]);
    uint32_t a2 = __float_as_uint(a[2]), a3 = __float_as_uint(a[3]);
    uint32_t b0 = __float_as_uint(b[0]), b1 = __float_as_uint(b[1]);
    asm volatile(
        "mma.sync.aligned.m16n8k8.row.col.f32.tf32.tf32.f32 "
        "{%0,%1,%2,%3}, {%4,%5,%6,%7}, {%8,%9}, {%0,%1,%2,%3};"
        : "+f"(c[0]), "+f"(c[1]), "+f"(c[2]), "+f"(c[3])
        : "r"(a0), "r"(a1), "r"(a2), "r"(a3), "r"(b0), "r"(b1));
}

// ---------------------------------------------------------------------------
// Generic TF32 tensor-core GEMM:  C = scale * (A @ opB(B)) [+ bias]
//   BM=128, BN=64, BK=32; 256 threads = 8 warps, warp tile 32x32
// MODE 0: projections (batch=1, bias, no trans)
// MODE 1: logits      (A=Q head view, B=K head view TRANSPOSED, scale, C=attn)
// MODE 2: ctx         (A=attn, B=V head view, C=ctx head view)
// ---------------------------------------------------------------------------
template<int MODE>
__global__ __launch_bounds__(256)
void gemm_tf32(const float* __restrict__ A, const float* __restrict__ B,
               const float* __restrict__ bias, float* __restrict__ C,
               int M, int N, int K, int lda, int ldb, int ldc, float scale) {
    constexpr bool TRANS_B = (MODE == 1);
    constexpr bool HAS_BIAS = (MODE == 0);

    // Batch offsets
    if (MODE == 1) {
        const int z = blockIdx.z;
        const size_t ho = (size_t)(z >> 4) * S_ * D_ + (size_t)(z & 15) * DH_;
        A += ho; B += ho; C += (size_t)z * S_ * S_;
    } else if (MODE == 2) {
        const int z = blockIdx.z;
        const size_t ho = (size_t)(z >> 4) * S_ * D_ + (size_t)(z & 15) * DH_;
        A += (size_t)z * S_ * S_; B += ho; C += ho;
    }

    __shared__ float As[32][136];   // [k][m], stride 136 % 32 == 8 -> conflict-free frags
    __shared__ float Bs[32][72];    // [k][n], stride 72 % 32 == 8

    const int t    = threadIdx.x;
    const int lane = t & 31;
    const int warp = t >> 5;
    const int wm   = (warp >> 1) * 32;     // warp row offset within block tile
    const int wn   = (warp & 1) * 32;      // warp col offset
    const int qr   = lane >> 2;            // lane / 4
    const int qc   = lane & 3;             // lane % 4
    const int row0 = blockIdx.y * 128;
    const int col0 = blockIdx.x * 64;

    float acc[2][4][4] = {};

    for (int k0 = 0; k0 < K; k0 += 32) {
        // ---- A tile: 128 rows x 32 k. Thread: row = t&127, 16 consecutive k.
        {
            const int r  = t & 127;
            const int kq = (t >> 7) * 16;
            const float* src = A + (size_t)(row0 + r) * lda + k0 + kq;
            #pragma unroll
            for (int i = 0; i < 4; i++) {
                float4 v = *(const float4*)(src + i * 4);
                As[kq + 4*i + 0][r] = to_tf32(v.x);
                As[kq + 4*i + 1][r] = to_tf32(v.y);
                As[kq + 4*i + 2][r] = to_tf32(v.z);
                As[kq + 4*i + 3][r] = to_tf32(v.w);
            }
        }
        // ---- B tile: 32 k x 64 n
        if (!TRANS_B) {
            const int kk = t >> 4;          // 0..15
            const int nq = (t & 15) * 4;
            #pragma unroll
            for (int p = 0; p < 2; p++) {
                const int k = kk + p * 16;
                float4 v = *(const float4*)(B + (size_t)(k0 + k) * ldb + col0 + nq);
                Bs[k][nq + 0] = to_tf32(v.x);
                Bs[k][nq + 1] = to_tf32(v.y);
                Bs[k][nq + 2] = to_tf32(v.z);
                Bs[k][nq + 3] = to_tf32(v.w);
            }
        } else {
            // Source is K[n][k] (row stride ldb); transpose into Bs[k][n].
            const int n  = t & 63;
            const int kq = (t >> 6) * 8;
            const float* src = B + (size_t)(col0 + n) * ldb + k0 + kq;
            #pragma unroll
            for (int p = 0; p < 2; p++) {
                float4 v = *(const float4*)(src + p * 4);
                Bs[kq + 4*p + 0][n] = to_tf32(v.x);
                Bs[kq + 4*p + 1][n] = to_tf32(v.y);
                Bs[kq + 4*p + 2][n] = to_tf32(v.z);
                Bs[kq + 4*p + 3][n] = to_tf32(v.w);
            }
        }
        __syncthreads();

        // ---- 4 k-steps of m16n8k8 per BK=32 tile
        #pragma unroll
        for (int ks = 0; ks < 4; ks++) {
            const int kb = ks * 8;
            float a[2][4], bfr[4][2];
            #pragma unroll
            for (int mt = 0; mt < 2; mt++) {
                const int m = wm + mt * 16 + qr;
                a[mt][0] = As[kb + qc    ][m];
                a[mt][1] = As[kb + qc    ][m + 8];
                a[mt][2] = As[kb + qc + 4][m];
                a[mt][3] = As[kb + qc + 4][m + 8];
            }
            #pragma unroll
            for (int nt = 0; nt < 4; nt++) {
                const int n = wn + nt * 8 + qr;
                bfr[nt][0] = Bs[kb + qc    ][n];
                bfr[nt][1] = Bs[kb + qc + 4][n];
            }
            #pragma unroll
            for (int mt = 0; mt < 2; mt++)
                #pragma unroll
                for (int nt = 0; nt < 4; nt++)
                    mma_tf32(acc[mt][nt], a[mt], bfr[nt]);
        }
        __syncthreads();
    }

    // ---- Epilogue
    #pragma unroll
    for (int mt = 0; mt < 2; mt++) {
        #pragma unroll
        for (int nt = 0; nt < 4; nt++) {
            const int r0 = row0 + wm + mt * 16 + qr;
            const int c0c = col0 + wn + nt * 8 + 2 * qc;
            float v0 = acc[mt][nt][0] * scale;
            float v1 = acc[mt][nt][1] * scale;
            float v2 = acc[mt][nt][2] * scale;
            float v3 = acc[mt][nt][3] * scale;
            if (HAS_BIAS) {
                v0 += bias[c0c];     v1 += bias[c0c + 1];
                v2 += bias[c0c];     v3 += bias[c0c + 1];
            }
            C[(size_t)r0 * ldc + c0c]           = v0;
            C[(size_t)r0 * ldc + c0c + 1]       = v1;
            C[(size_t)(r0 + 8) * ldc + c0c]     = v2;
            C[(size_t)(r0 + 8) * ldc + c0c + 1] = v3;
        }
    }
}

// ---------------------------------------------------------------------------
// Row softmax over S=1024, in place on g_attn; optional duplicate to attn_out
// ---------------------------------------------------------------------------
__global__ __launch_bounds__(256)
void softmax_kernel(float* __restrict__ attn_out) {
    const size_t row = blockIdx.x;
    float* p = g_attn + row * S_;
    const int t = threadIdx.x;

    float v[4];
    float m = -3.402823466e38f;
    #pragma unroll
    for (int i = 0; i < 4; i++) { v[i] = p[t + i * 256]; m = fmaxf(m, v[i]); }

    __shared__ float red[8];
    #pragma unroll
    for (int o = 16; o; o >>= 1) m = fmaxf(m, __shfl_xor_sync(0xffffffffu, m, o));
    if ((t & 31) == 0) red[t >> 5] = m;
    __syncthreads();
    m = red[0];
    #pragma unroll
    for (int w = 1; w < 8; w++) m = fmaxf(m, red[w]);
    __syncthreads();

    float s = 0.f;
    #pragma unroll
    for (int i = 0; i < 4; i++) { v[i] = __expf(v[i] - m); s += v[i]; }
    #pragma unroll
    for (int o = 16; o; o >>= 1) s += __shfl_xor_sync(0xffffffffu, s, o);
    if ((t & 31) == 0) red[t >> 5] = s;
    __syncthreads();
    s = 0.f;
    #pragma unroll
    for (int w = 0; w < 8; w++) s += red[w];

    const float inv = 1.f / s;
    #pragma unroll
    for (int i = 0; i < 4; i++) {
        float r = v[i] * inv;
        p[t + i * 256] = r;
        if (attn_out) attn_out[row * S_ + t + i * 256] = r;
    }
}

// ---------------------------------------------------------------------------
// Launch
// Inputs: 0 query, 1 key, 2 value, 3 Wq, 4 bq, 5 Wk, 6 bk, 7 Wv, 8 bv, 9 Wo, 10 bo
// Output: out [B,S,D]  (+ attn [B,H,S,S] appended if out_size covers it)
// ---------------------------------------------------------------------------
extern "C" void kernel_launch(void* const* d_in, const int* in_sizes, int n_in,
                              void* d_out, int out_size) {
    const float* query = (const float*)d_in[0];
    const float* key   = (const float*)d_in[1];
    const float* value = (const float*)d_in[2];
    const float* Wq    = (const float*)d_in[3];
    const float* bq    = (const float*)d_in[4];
    const float* Wk    = (const float*)d_in[5];
    const float* bk    = (const float*)d_in[6];
    const float* Wv    = (const float*)d_in[7];
    const float* bv    = (const float*)d_in[8];
    const float* Wo    = (const float*)d_in[9];
    const float* bo    = (const float*)d_in[10];
    float* out = (float*)d_out;

    float *q_ptr, *k_ptr, *v_ptr, *ctx_ptr, *attn_ptr;
    cudaGetSymbolAddress((void**)&q_ptr,    g_q);
    cudaGetSymbolAddress((void**)&k_ptr,    g_k);
    cudaGetSymbolAddress((void**)&v_ptr,    g_v);
    cudaGetSymbolAddress((void**)&ctx_ptr,  g_ctx);
    cudaGetSymbolAddress((void**)&attn_ptr, g_attn);

    const long long bhss = (long long)B_ * H_ * S_ * S_;
    float* attn_out = nullptr;
    if ((long long)out_size >= (long long)BSD_ + bhss)
        attn_out = out + BSD_;

    // Projections: M=8192, N=1024, K=1024
    dim3 gproj(D_ / 64, (B_ * S_) / 128);       // (16, 64)
    gemm_tf32<0><<<gproj, 256>>>(query, Wq, bq, q_ptr, B_ * S_, D_, D_, D_, D_, D_, 1.f);
    gemm_tf32<0><<<gproj, 256>>>(key,   Wk, bk, k_ptr, B_ * S_, D_, D_, D_, D_, D_, 1.f);
    gemm_tf32<0><<<gproj, 256>>>(value, Wv, bv, v_ptr, B_ * S_, D_, D_, D_, D_, D_, 1.f);

    // Logits: per (b,h) GEMM 1024x1024x64, B transposed, scaled
    dim3 glog(S_ / 64, S_ / 128, B_ * H_);      // (16, 8, 128)
    gemm_tf32<1><<<glog, 256>>>(q_ptr, k_ptr, nullptr, attn_ptr,
                                S_, S_, DH_, D_, D_, S_, SCALE_);

    // Softmax (in place) + optional duplicate into output attn region
    softmax_kernel<<<B_ * H_ * S_, 256>>>(attn_out);

    // ctx: per (b,h) GEMM 1024x64x1024
    dim3 gctx(1, S_ / 128, B_ * H_);            // (1, 8, 128)
    gemm_tf32<2><<<gctx, 256>>>(attn_ptr, v_ptr, nullptr, ctx_ptr,
                                S_, DH_, S_, S_, D_, D_, 1.f);

    // Output projection
    gemm_tf32<0><<<gproj, 256>>>(ctx_ptr, Wo, bo, out, B_ * S_, D_, D_, D_, D_, D_, 1.f);
}

// round 3
// speedup vs baseline: 3.8191x; 1.9702x over previous
#include <cuda_runtime.h>
#include <cstdint>

#define B_  8
#define S_  1024
#define D_  1024
#define H_  16
#define DH_ 64
#define BSD_ (B_ * S_ * D_)
#define BHS_ (B_ * H_ * S_)
#define SCALE_ 0.125f

// ---------------------------------------------------------------------------
// Scratch (__device__ globals; alloc-free rule)
// ---------------------------------------------------------------------------
__device__ float g_q[BSD_];
__device__ float g_k[BSD_];
__device__ float g_v[BSD_];
__device__ float g_ctx[BSD_];
__device__ float g_tx[BSD_];                       // tf32-rounded input scratch
__device__ float g_tw[D_ * D_];                    // tf32-rounded weight scratch
__device__ float g_rowsum[BHS_];
__device__ float g_attn_fb[(size_t)B_ * H_ * S_ * S_];  // fallback exp buffer

// ---------------------------------------------------------------------------
// Helpers
// ---------------------------------------------------------------------------
__device__ __forceinline__ float to_tf32(float x) {
    uint32_t u;
    asm("cvt.rna.tf32.f32 %0, %1;" : "=r"(u) : "f"(x));
    return __uint_as_float(u);
}

__device__ __forceinline__ void mma_tf32(float c[4],
                                         const float a[4], const float b[2]) {
    uint32_t a0 = __float_as_uint(a[0]), a1 = __float_as_uint(a[1]);
    uint32_t a2 = __float_as_uint(a[2]), a3 = __float_as_uint(a[3]);
    uint32_t b0 = __float_as_uint(b[0]), b1 = __float_as_uint(b[1]);
    asm volatile(
        "mma.sync.aligned.m16n8k8.row.col.f32.tf32.tf32.f32 "
        "{%0,%1,%2,%3}, {%4,%5,%6,%7}, {%8,%9}, {%0,%1,%2,%3};"
        : "+f"(c[0]), "+f"(c[1]), "+f"(c[2]), "+f"(c[3])
        : "r"(a0), "r"(a1), "r"(a2), "r"(a3), "r"(b0), "r"(b1));
}

__device__ __forceinline__ void cpa16(uint32_t dst, const void* src) {
    asm volatile("cp.async.cg.shared.global [%0], [%1], 16;\n" :: "r"(dst), "l"(src));
}
__device__ __forceinline__ void cp_commit() { asm volatile("cp.async.commit_group;\n"); }
__device__ __forceinline__ void cp_wait0()  { asm volatile("cp.async.wait_group 0;\n"); }
__device__ __forceinline__ void cp_wait1()  { asm volatile("cp.async.wait_group 1;\n"); }

// ---------------------------------------------------------------------------
// Elementwise tf32 rounding (prepares GEMM operands)
// ---------------------------------------------------------------------------
__global__ __launch_bounds__(256)
void cvt_rna_kernel(const float4* __restrict__ in, float4* __restrict__ out, int n4) {
    int i = blockIdx.x * 256 + threadIdx.x;
    if (i < n4) {
        float4 v = in[i];
        v.x = to_tf32(v.x); v.y = to_tf32(v.y);
        v.z = to_tf32(v.z); v.w = to_tf32(v.w);
        out[i] = v;
    }
}

// ---------------------------------------------------------------------------
// Projection GEMM: C[8192,1024] = A[8192,1024] @ W[1024,1024] + bias
// BM=128, BN=128, BK=32, 2-stage cp.async, 8 warps (2x4), warp tile 64x32
// A/W must be pre-rounded to tf32. ROUND: round output (for q/k/v).
// ---------------------------------------------------------------------------
#define PA_ST (128 * 36)    // A stage floats
#define PB_ST (32 * 136)    // B stage floats

__device__ __forceinline__ void proj_load_stage(
    uint32_t asb, uint32_t bsb, const float* A, const float* W,
    int row0, int col0, int k0, int st, int t) {
    #pragma unroll
    for (int i = 0; i < 4; i++) {
        int idx = t + i * 256;
        int m = idx >> 3, c = idx & 7;
        cpa16(asb + (uint32_t)((st * PA_ST + m * 36 + c * 4) * 4),
              A + (size_t)(row0 + m) * D_ + k0 + c * 4);
    }
    #pragma unroll
    for (int i = 0; i < 4; i++) {
        int idx = t + i * 256;
        int k = idx >> 5, c = idx & 31;
        cpa16(bsb + (uint32_t)((st * PB_ST + k * 136 + c * 4) * 4),
              W + (size_t)(k0 + k) * D_ + col0 + c * 4);
    }
    cp_commit();
}

template<bool ROUND>
__global__ __launch_bounds__(256)
void proj_gemm(const float* __restrict__ A, const float* __restrict__ W,
               const float* __restrict__ bias, float* __restrict__ C) {
    extern __shared__ float sm[];
    float* As = sm;
    float* Bs = sm + 2 * PA_ST;
    const int t = threadIdx.x;
    const int row0 = blockIdx.y * 128, col0 = blockIdx.x * 128;
    const uint32_t asb = (uint32_t)__cvta_generic_to_shared(As);
    const uint32_t bsb = (uint32_t)__cvta_generic_to_shared(Bs);

    const int lane = t & 31, warp = t >> 5;
    const int wm = (warp >> 2) * 64, wn = (warp & 3) * 32;
    const int qr = lane >> 2, qc = lane & 3;

    float acc[4][4][4] = {};

    proj_load_stage(asb, bsb, A, W, row0, col0, 0, 0, t);

    for (int kt = 0; kt < 32; kt++) {
        if (kt < 31) {
            proj_load_stage(asb, bsb, A, W, row0, col0, (kt + 1) * 32, (kt + 1) & 1, t);
            cp_wait1();
        } else {
            cp_wait0();
        }
        __syncthreads();

        const float* as = As + (kt & 1) * PA_ST;
        const float* bs = Bs + (kt & 1) * PB_ST;
        #pragma unroll
        for (int ks = 0; ks < 4; ks++) {
            const int kb = ks * 8;
            float a[4][4], b[4][2];
            #pragma unroll
            for (int mt = 0; mt < 4; mt++) {
                const float* ap = as + (wm + mt * 16 + qr) * 36 + kb + qc;
                a[mt][0] = ap[0];        a[mt][1] = ap[8 * 36];
                a[mt][2] = ap[4];        a[mt][3] = ap[8 * 36 + 4];
            }
            #pragma unroll
            for (int nt = 0; nt < 4; nt++) {
                const float* bp = bs + (kb + qc) * 136 + wn + nt * 8 + qr;
                b[nt][0] = bp[0];        b[nt][1] = bp[4 * 136];
            }
            #pragma unroll
            for (int mt = 0; mt < 4; mt++)
                #pragma unroll
                for (int nt = 0; nt < 4; nt++)
                    mma_tf32(acc[mt][nt], a[mt], b[nt]);
        }
        __syncthreads();
    }

    #pragma unroll
    for (int mt = 0; mt < 4; mt++) {
        #pragma unroll
        for (int nt = 0; nt < 4; nt++) {
            const int r = row0 + wm + mt * 16 + qr;
            const int c = col0 + wn + nt * 8 + 2 * qc;
            const float b0 = bias[c], b1 = bias[c + 1];
            float v0 = acc[mt][nt][0] + b0, v1 = acc[mt][nt][1] + b1;
            float v2 = acc[mt][nt][2] + b0, v3 = acc[mt][nt][3] + b1;
            if (ROUND) {
                v0 = to_tf32(v0); v1 = to_tf32(v1);
                v2 = to_tf32(v2); v3 = to_tf32(v3);
            }
            *(float2*)(C + (size_t)r * D_ + c)       = make_float2(v0, v1);
            *(float2*)(C + (size_t)(r + 8) * D_ + c) = make_float2(v2, v3);
        }
    }
}

// ---------------------------------------------------------------------------
// Logits + exp: expb[z,i,j] = exp(scale * q[i]·k[j]); rowsum += partials
// BM=128, BN=64, K=64 (single shot). Q/K pre-rounded. No transposes needed.
// ---------------------------------------------------------------------------
__global__ __launch_bounds__(256)
void logits_gemm(const float* __restrict__ Q, const float* __restrict__ K,
                 float* __restrict__ expb, float* __restrict__ rowsum) {
    extern __shared__ float sm[];
    float* Qs = sm;              // [128][68]
    float* Ks = sm + 128 * 68;   // [64][68]
    const int z = blockIdx.z;
    const size_t ho = (size_t)(z >> 4) * S_ * D_ + (size_t)(z & 15) * DH_;
    const float* Qg = Q + ho;
    const float* Kg = K + ho;
    float* Ob = expb + (size_t)z * S_ * S_;
    const int t = threadIdx.x;
    const int row0 = blockIdx.y * 128, col0 = blockIdx.x * 64;
    const uint32_t qsb = (uint32_t)__cvta_generic_to_shared(Qs);
    const uint32_t ksb = (uint32_t)__cvta_generic_to_shared(Ks);

    #pragma unroll
    for (int i = 0; i < 8; i++) {
        int idx = t + i * 256;
        int m = idx >> 4, c = idx & 15;
        cpa16(qsb + (uint32_t)((m * 68 + c * 4) * 4),
              Qg + (size_t)(row0 + m) * D_ + c * 4);
    }
    #pragma unroll
    for (int i = 0; i < 4; i++) {
        int idx = t + i * 256;
        int n = idx >> 4, c = idx & 15;
        cpa16(ksb + (uint32_t)((n * 68 + c * 4) * 4),
              Kg + (size_t)(col0 + n) * D_ + c * 4);
    }
    cp_commit();
    cp_wait0();
    __syncthreads();

    const int lane = t & 31, warp = t >> 5;
    const int wm = (warp >> 1) * 32, wn = (warp & 1) * 32;
    const int qr = lane >> 2, qc = lane & 3;

    float acc[2][4][4] = {};
    #pragma unroll
    for (int ks = 0; ks < 8; ks++) {
        const int kb = ks * 8;
        float a[2][4], b[4][2];
        #pragma unroll
        for (int mt = 0; mt < 2; mt++) {
            const float* ap = Qs + (wm + mt * 16 + qr) * 68 + kb + qc;
            a[mt][0] = ap[0];       a[mt][1] = ap[8 * 68];
            a[mt][2] = ap[4];       a[mt][3] = ap[8 * 68 + 4];
        }
        #pragma unroll
        for (int nt = 0; nt < 4; nt++) {
            const float* bp = Ks + (wn + nt * 8 + qr) * 68 + kb + qc;
            b[nt][0] = bp[0];       b[nt][1] = bp[4];
        }
        #pragma unroll
        for (int mt = 0; mt < 2; mt++)
            #pragma unroll
            for (int nt = 0; nt < 4; nt++)
                mma_tf32(acc[mt][nt], a[mt], b[nt]);
    }

    // exp + store + row-sum partials
    #pragma unroll
    for (int mt = 0; mt < 2; mt++) {
        float p0 = 0.f, p1 = 0.f;
        const int r = row0 + wm + mt * 16 + qr;
        #pragma unroll
        for (int nt = 0; nt < 4; nt++) {
            const int c = col0 + wn + nt * 8 + 2 * qc;
            float e0 = __expf(acc[mt][nt][0] * SCALE_);
            float e1 = __expf(acc[mt][nt][1] * SCALE_);
            float e2 = __expf(acc[mt][nt][2] * SCALE_);
            float e3 = __expf(acc[mt][nt][3] * SCALE_);
            p0 += e0 + e1;  p1 += e2 + e3;
            *(float2*)(Ob + (size_t)r * S_ + c)       = make_float2(e0, e1);
            *(float2*)(Ob + (size_t)(r + 8) * S_ + c) = make_float2(e2, e3);
        }
        p0 += __shfl_xor_sync(0xffffffffu, p0, 1);
        p0 += __shfl_xor_sync(0xffffffffu, p0, 2);
        p1 += __shfl_xor_sync(0xffffffffu, p1, 1);
        p1 += __shfl_xor_sync(0xffffffffu, p1, 2);
        if (qc == 0) {
            atomicAdd(&rowsum[z * S_ + r], p0);
            atomicAdd(&rowsum[z * S_ + r + 8], p1);
        }
    }
}

// ---------------------------------------------------------------------------
// ctx GEMM + attn normalization: P (exp) is normalized in place in d_out,
// ctx[b,i,h,:] = (P/rowsum) @ V, written tf32-rounded.
// BM=128, BN=64 (full head dim), BK=32; V double-buffered cp.async.
// ---------------------------------------------------------------------------
#define CV_ST (32 * 72)

__global__ __launch_bounds__(256)
void ctx_gemm(float* __restrict__ P, const float* __restrict__ V,
              const float* __restrict__ rowsum, float* __restrict__ C) {
    extern __shared__ float sm[];
    float* As = sm;              // [128][36]
    float* Vs = sm + 128 * 36;   // 2 x [32][72]
    const int z = blockIdx.z;
    const size_t ho = (size_t)(z >> 4) * S_ * D_ + (size_t)(z & 15) * DH_;
    float* Pb = P + (size_t)z * S_ * S_;
    const float* Vb = V + ho;
    float* Ob = C + ho;
    const int t = threadIdx.x;
    const int row0 = blockIdx.y * 128;
    const uint32_t vsb = (uint32_t)__cvta_generic_to_shared(Vs);

    const int am = t >> 1;                 // row this thread stages
    const int ac0 = (t & 1) * 4;           // first float4 index in the 32-wide chunk
    const float inv = 1.0f / rowsum[z * S_ + row0 + am];

    const int lane = t & 31, warp = t >> 5;
    const int wm = (warp >> 1) * 32, wn = (warp & 1) * 32;
    const int qr = lane >> 2, qc = lane & 3;

    float acc[2][4][4] = {};

    // V stage 0
    #pragma unroll
    for (int i = 0; i < 2; i++) {
        int idx = t + i * 256;
        int k = idx >> 4, c = idx & 15;
        cpa16(vsb + (uint32_t)((k * 72 + c * 4) * 4),
              Vb + (size_t)k * D_ + c * 4);
    }
    cp_commit();

    // A prefetch for kt=0
    float4 apre[4];
    {
        const float* src = Pb + (size_t)(row0 + am) * S_;
        #pragma unroll
        for (int i = 0; i < 4; i++) apre[i] = *(const float4*)(src + (ac0 + i) * 4);
    }

    for (int kt = 0; kt < 32; kt++) {
        const int k0 = kt * 32;
        // Stage A: normalize (write back to d_out) + tf32-round into smem
        {
            float* dstg = Pb + (size_t)(row0 + am) * S_ + k0;
            float* dsts = As + am * 36;
            #pragma unroll
            for (int i = 0; i < 4; i++) {
                float4 v = apre[i];
                v.x *= inv; v.y *= inv; v.z *= inv; v.w *= inv;
                *(float4*)(dstg + (ac0 + i) * 4) = v;
                float* d = dsts + (ac0 + i) * 4;
                d[0] = to_tf32(v.x); d[1] = to_tf32(v.y);
                d[2] = to_tf32(v.z); d[3] = to_tf32(v.w);
            }
        }
        if (kt < 31) {
            // prefetch next A chunk
            const float* src = Pb + (size_t)(row0 + am) * S_ + k0 + 32;
            #pragma unroll
            for (int i = 0; i < 4; i++) apre[i] = *(const float4*)(src + (ac0 + i) * 4);
            // next V stage
            const int st = (kt + 1) & 1;
            #pragma unroll
            for (int i = 0; i < 2; i++) {
                int idx = t + i * 256;
                int k = idx >> 4, c = idx & 15;
                cpa16(vsb + (uint32_t)((st * CV_ST + k * 72 + c * 4) * 4),
                      Vb + (size_t)(k0 + 32 + k) * D_ + c * 4);
            }
            cp_commit();
            cp_wait1();
        } else {
            cp_wait0();
        }
        __syncthreads();

        const float* vs = Vs + (kt & 1) * CV_ST;
        #pragma unroll
        for (int ks = 0; ks < 4; ks++) {
            const int kb = ks * 8;
            float a[2][4], b[4][2];
            #pragma unroll
            for (int mt = 0; mt < 2; mt++) {
                const float* ap = As + (wm + mt * 16 + qr) * 36 + kb + qc;
                a[mt][0] = ap[0];       a[mt][1] = ap[8 * 36];
                a[mt][2] = ap[4];       a[mt][3] = ap[8 * 36 + 4];
            }
            #pragma unroll
            for (int nt = 0; nt < 4; nt++) {
                const float* bp = vs + (kb + qc) * 72 + wn + nt * 8 + qr;
                b[nt][0] = bp[0];       b[nt][1] = bp[4 * 72];
            }
            #pragma unroll
            for (int mt = 0; mt < 2; mt++)
                #pragma unroll
                for (int nt = 0; nt < 4; nt++)
                    mma_tf32(acc[mt][nt], a[mt], b[nt]);
        }
        __syncthreads();
    }

    #pragma unroll
    for (int mt = 0; mt < 2; mt++) {
        #pragma unroll
        for (int nt = 0; nt < 4; nt++) {
            const int r = row0 + wm + mt * 16 + qr;
            const int c = wn + nt * 8 + 2 * qc;
            float v0 = to_tf32(acc[mt][nt][0]), v1 = to_tf32(acc[mt][nt][1]);
            float v2 = to_tf32(acc[mt][nt][2]), v3 = to_tf32(acc[mt][nt][3]);
            *(float2*)(Ob + (size_t)r * D_ + c)       = make_float2(v0, v1);
            *(float2*)(Ob + (size_t)(r + 8) * D_ + c) = make_float2(v2, v3);
        }
    }
}

// ---------------------------------------------------------------------------
// Launch
// ---------------------------------------------------------------------------
extern "C" void kernel_launch(void* const* d_in, const int* in_sizes, int n_in,
                              void* d_out, int out_size) {
    const float* query = (const float*)d_in[0];
    const float* key   = (const float*)d_in[1];
    const float* value = (const float*)d_in[2];
    const float* Wq    = (const float*)d_in[3];
    const float* bq    = (const float*)d_in[4];
    const float* Wk    = (const float*)d_in[5];
    const float* bk    = (const float*)d_in[6];
    const float* Wv    = (const float*)d_in[7];
    const float* bv    = (const float*)d_in[8];
    const float* Wo    = (const float*)d_in[9];
    const float* bo    = (const float*)d_in[10];
    float* out = (float*)d_out;

    float *q_ptr, *k_ptr, *v_ptr, *ctx_ptr, *tx_ptr, *tw_ptr, *rs_ptr, *fb_ptr;
    cudaGetSymbolAddress((void**)&q_ptr,   g_q);
    cudaGetSymbolAddress((void**)&k_ptr,   g_k);
    cudaGetSymbolAddress((void**)&v_ptr,   g_v);
    cudaGetSymbolAddress((void**)&ctx_ptr, g_ctx);
    cudaGetSymbolAddress((void**)&tx_ptr,  g_tx);
    cudaGetSymbolAddress((void**)&tw_ptr,  g_tw);
    cudaGetSymbolAddress((void**)&rs_ptr,  g_rowsum);
    cudaGetSymbolAddress((void**)&fb_ptr,  g_attn_fb);

    const long long bhss = (long long)B_ * H_ * S_ * S_;
    float* expb = fb_ptr;
    if ((long long)out_size >= (long long)BSD_ + bhss)
        expb = out + BSD_;

    const int proj_smem   = (2 * PA_ST + 2 * PB_ST) * 4;        // 71680
    const int logits_smem = (128 * 68 + 64 * 68) * 4;           // 52224
    const int ctx_smem    = (128 * 36 + 2 * CV_ST) * 4;         // 36864
    cudaFuncSetAttribute(proj_gemm<true>,  cudaFuncAttributeMaxDynamicSharedMemorySize, proj_smem);
    cudaFuncSetAttribute(proj_gemm<false>, cudaFuncAttributeMaxDynamicSharedMemorySize, proj_smem);
    cudaFuncSetAttribute(logits_gemm,      cudaFuncAttributeMaxDynamicSharedMemorySize, logits_smem);
    cudaFuncSetAttribute(ctx_gemm,         cudaFuncAttributeMaxDynamicSharedMemorySize, ctx_smem);

    const int n4x = BSD_ / 4, n4w = (D_ * D_) / 4;
    dim3 gproj(D_ / 128, (B_ * S_) / 128);          // (8, 64)

    // Q projection
    cvt_rna_kernel<<<(n4x + 255) / 256, 256>>>((const float4*)query, (float4*)tx_ptr, n4x);
    cvt_rna_kernel<<<(n4w + 255) / 256, 256>>>((const float4*)Wq, (float4*)tw_ptr, n4w);
    proj_gemm<true><<<gproj, 256, proj_smem>>>(tx_ptr, tw_ptr, bq, q_ptr);
    // K projection
    cvt_rna_kernel<<<(n4x + 255) / 256, 256>>>((const float4*)key, (float4*)tx_ptr, n4x);
    cvt_rna_kernel<<<(n4w + 255) / 256, 256>>>((const float4*)Wk, (float4*)tw_ptr, n4w);
    proj_gemm<true><<<gproj, 256, proj_smem>>>(tx_ptr, tw_ptr, bk, k_ptr);
    // V projection
    cvt_rna_kernel<<<(n4x + 255) / 256, 256>>>((const float4*)value, (float4*)tx_ptr, n4x);
    cvt_rna_kernel<<<(n4w + 255) / 256, 256>>>((const float4*)Wv, (float4*)tw_ptr, n4w);
    proj_gemm<true><<<gproj, 256, proj_smem>>>(tx_ptr, tw_ptr, bv, v_ptr);

    // Attention
    cudaMemsetAsync(rs_ptr, 0, BHS_ * sizeof(float));
    logits_gemm<<<dim3(S_ / 64, S_ / 128, B_ * H_), 256, logits_smem>>>(q_ptr, k_ptr, expb, rs_ptr);
    ctx_gemm<<<dim3(1, S_ / 128, B_ * H_), 256, ctx_smem>>>(expb, v_ptr, rs_ptr, ctx_ptr);

    // Output projection (no rounding of final output)
    cvt_rna_kernel<<<(n4w + 255) / 256, 256>>>((const float4*)Wo, (float4*)tw_ptr, n4w);
    proj_gemm<false><<<gproj, 256, proj_smem>>>(ctx_ptr, tw_ptr, bo, out);
}

// round 4
// speedup vs baseline: 4.0357x; 1.0567x over previous
#include <cuda_runtime.h>
#include <cstdint>

#define B_  8
#define S_  1024
#define D_  1024
#define H_  16
#define DH_ 64
#define BSD_ (B_ * S_ * D_)
#define BHS_ (B_ * H_ * S_)
#define SCALE_ 0.125f

// ---------------------------------------------------------------------------
// Scratch (__device__ globals; alloc-free rule)
// ---------------------------------------------------------------------------
__device__ float g_q[BSD_];
__device__ float g_k[BSD_];
__device__ float g_v[BSD_];
__device__ float g_ctx[BSD_];
__device__ float g_tx[BSD_];
__device__ float g_tw[D_ * D_];
__device__ float g_rowsum[BHS_];
__device__ float g_attn_fb[(size_t)B_ * H_ * S_ * S_];  // fallback attn sink

// ---------------------------------------------------------------------------
// Helpers
// ---------------------------------------------------------------------------
__device__ __forceinline__ float to_tf32(float x) {
    uint32_t u;
    asm("cvt.rna.tf32.f32 %0, %1;" : "=r"(u) : "f"(x));
    return __uint_as_float(u);
}

__device__ __forceinline__ void mma_tf32(float c[4],
                                         const float a[4], const float b[2]) {
    uint32_t a0 = __float_as_uint(a[0]), a1 = __float_as_uint(a[1]);
    uint32_t a2 = __float_as_uint(a[2]), a3 = __float_as_uint(a[3]);
    uint32_t b0 = __float_as_uint(b[0]), b1 = __float_as_uint(b[1]);
    asm volatile(
        "mma.sync.aligned.m16n8k8.row.col.f32.tf32.tf32.f32 "
        "{%0,%1,%2,%3}, {%4,%5,%6,%7}, {%8,%9}, {%0,%1,%2,%3};"
        : "+f"(c[0]), "+f"(c[1]), "+f"(c[2]), "+f"(c[3])
        : "r"(a0), "r"(a1), "r"(a2), "r"(a3), "r"(b0), "r"(b1));
}

__device__ __forceinline__ void cpa16(uint32_t dst, const void* src) {
    asm volatile("cp.async.cg.shared.global [%0], [%1], 16;\n" :: "r"(dst), "l"(src));
}
__device__ __forceinline__ void cp_commit() { asm volatile("cp.async.commit_group;\n"); }
__device__ __forceinline__ void cp_wait0()  { asm volatile("cp.async.wait_group 0;\n"); }
__device__ __forceinline__ void cp_wait1()  { asm volatile("cp.async.wait_group 1;\n"); }

// ---------------------------------------------------------------------------
// Elementwise tf32 rounding
// ---------------------------------------------------------------------------
__global__ __launch_bounds__(256)
void cvt_rna_kernel(const float4* __restrict__ in, float4* __restrict__ out, int n4) {
    int i = blockIdx.x * 256 + threadIdx.x;
    if (i < n4) {
        float4 v = in[i];
        v.x = to_tf32(v.x); v.y = to_tf32(v.y);
        v.z = to_tf32(v.z); v.w = to_tf32(v.w);
        out[i] = v;
    }
}

// ---------------------------------------------------------------------------
// Projection GEMM (unchanged from R3): C = A @ W + bias, 128x128x32 tiles
// ---------------------------------------------------------------------------
#define PA_ST (128 * 36)
#define PB_ST (32 * 136)

__device__ __forceinline__ void proj_load_stage(
    uint32_t asb, uint32_t bsb, const float* A, const float* W,
    int row0, int col0, int k0, int st, int t) {
    #pragma unroll
    for (int i = 0; i < 4; i++) {
        int idx = t + i * 256;
        int m = idx >> 3, c = idx & 7;
        cpa16(asb + (uint32_t)((st * PA_ST + m * 36 + c * 4) * 4),
              A + (size_t)(row0 + m) * D_ + k0 + c * 4);
    }
    #pragma unroll
    for (int i = 0; i < 4; i++) {
        int idx = t + i * 256;
        int k = idx >> 5, c = idx & 31;
        cpa16(bsb + (uint32_t)((st * PB_ST + k * 136 + c * 4) * 4),
              W + (size_t)(k0 + k) * D_ + col0 + c * 4);
    }
    cp_commit();
}

template<bool ROUND>
__global__ __launch_bounds__(256)
void proj_gemm(const float* __restrict__ A, const float* __restrict__ W,
               const float* __restrict__ bias, float* __restrict__ C) {
    extern __shared__ float sm[];
    float* As = sm;
    float* Bs = sm + 2 * PA_ST;
    const int t = threadIdx.x;
    const int row0 = blockIdx.y * 128, col0 = blockIdx.x * 128;
    const uint32_t asb = (uint32_t)__cvta_generic_to_shared(As);
    const uint32_t bsb = (uint32_t)__cvta_generic_to_shared(Bs);

    const int lane = t & 31, warp = t >> 5;
    const int wm = (warp >> 2) * 64, wn = (warp & 3) * 32;
    const int qr = lane >> 2, qc = lane & 3;

    float acc[4][4][4] = {};

    proj_load_stage(asb, bsb, A, W, row0, col0, 0, 0, t);

    for (int kt = 0; kt < 32; kt++) {
        if (kt < 31) {
            proj_load_stage(asb, bsb, A, W, row0, col0, (kt + 1) * 32, (kt + 1) & 1, t);
            cp_wait1();
        } else {
            cp_wait0();
        }
        __syncthreads();

        const float* as = As + (kt & 1) * PA_ST;
        const float* bs = Bs + (kt & 1) * PB_ST;
        #pragma unroll
        for (int ks = 0; ks < 4; ks++) {
            const int kb = ks * 8;
            float a[4][4], b[4][2];
            #pragma unroll
            for (int mt = 0; mt < 4; mt++) {
                const float* ap = as + (wm + mt * 16 + qr) * 36 + kb + qc;
                a[mt][0] = ap[0];        a[mt][1] = ap[8 * 36];
                a[mt][2] = ap[4];        a[mt][3] = ap[8 * 36 + 4];
            }
            #pragma unroll
            for (int nt = 0; nt < 4; nt++) {
                const float* bp = bs + (kb + qc) * 136 + wn + nt * 8 + qr;
                b[nt][0] = bp[0];        b[nt][1] = bp[4 * 136];
            }
            #pragma unroll
            for (int mt = 0; mt < 4; mt++)
                #pragma unroll
                for (int nt = 0; nt < 4; nt++)
                    mma_tf32(acc[mt][nt], a[mt], b[nt]);
        }
        __syncthreads();
    }

    #pragma unroll
    for (int mt = 0; mt < 4; mt++) {
        #pragma unroll
        for (int nt = 0; nt < 4; nt++) {
            const int r = row0 + wm + mt * 16 + qr;
            const int c = col0 + wn + nt * 8 + 2 * qc;
            const float b0 = bias[c], b1 = bias[c + 1];
            float v0 = acc[mt][nt][0] + b0, v1 = acc[mt][nt][1] + b1;
            float v2 = acc[mt][nt][2] + b0, v3 = acc[mt][nt][3] + b1;
            if (ROUND) {
                v0 = to_tf32(v0); v1 = to_tf32(v1);
                v2 = to_tf32(v2); v3 = to_tf32(v3);
            }
            *(float2*)(C + (size_t)r * D_ + c)       = make_float2(v0, v1);
            *(float2*)(C + (size_t)(r + 8) * D_ + c) = make_float2(v2, v3);
        }
    }
}

// ---------------------------------------------------------------------------
// Pass A: rowsum[z, i] = sum_j exp(scale * q_i . k_j)
// Block: 128 q-rows x all 1024 j. Q tile resident; K in 128-j tiles.
// No global atomics -> deterministic.
// ---------------------------------------------------------------------------
__global__ __launch_bounds__(256)
void rowsum_kernel(const float* __restrict__ Q, const float* __restrict__ K,
                   float* __restrict__ rowsum) {
    extern __shared__ float sm[];
    float* Qs  = sm;                    // [128][68]
    float* Ks  = sm + 128 * 68;        // [128][68]
    float* prt = sm + 2 * 128 * 68;    // [2][128]

    const int z = blockIdx.y;
    const size_t ho = (size_t)(z >> 4) * S_ * D_ + (size_t)(z & 15) * DH_;
    const float* Qg = Q + ho;
    const float* Kg = K + ho;
    const int t = threadIdx.x;
    const int row0 = blockIdx.x * 128;
    const uint32_t qsb = (uint32_t)__cvta_generic_to_shared(Qs);
    const uint32_t ksb = (uint32_t)__cvta_generic_to_shared(Ks);

    prt[t] = 0.f;   // 256 floats = whole [2][128]

    // Q tile: 128 rows x 64 d
    #pragma unroll
    for (int i = 0; i < 8; i++) {
        int idx = t + i * 256;
        int m = idx >> 4, c = idx & 15;
        cpa16(qsb + (uint32_t)((m * 68 + c * 4) * 4),
              Qg + (size_t)(row0 + m) * D_ + c * 4);
    }

    const int lane = t & 31, warp = t >> 5;
    const int wm = (warp >> 1) * 32;
    const int wj = (warp & 1) * 64;
    const int qr = lane >> 2, qc = lane & 3;

    float prs[2][2] = {};   // [mt][row-half]

    for (int jt = 0; jt < 8; jt++) {
        // K tile: 128 j-rows x 64 d
        #pragma unroll
        for (int i = 0; i < 8; i++) {
            int idx = t + i * 256;
            int n = idx >> 4, c = idx & 15;
            cpa16(ksb + (uint32_t)((n * 68 + c * 4) * 4),
                  Kg + (size_t)(jt * 128 + n) * D_ + c * 4);
        }
        cp_commit();
        cp_wait0();
        __syncthreads();

        float acc[2][8][4] = {};
        #pragma unroll
        for (int ks = 0; ks < 8; ks++) {
            const int kb = ks * 8;
            float a[2][4], b[8][2];
            #pragma unroll
            for (int mt = 0; mt < 2; mt++) {
                const float* ap = Qs + (wm + mt * 16 + qr) * 68 + kb + qc;
                a[mt][0] = ap[0];       a[mt][1] = ap[8 * 68];
                a[mt][2] = ap[4];       a[mt][3] = ap[8 * 68 + 4];
            }
            #pragma unroll
            for (int nt = 0; nt < 8; nt++) {
                const float* bp = Ks + (wj + nt * 8 + qr) * 68 + kb + qc;
                b[nt][0] = bp[0];       b[nt][1] = bp[4];
            }
            #pragma unroll
            for (int mt = 0; mt < 2; mt++)
                #pragma unroll
                for (int nt = 0; nt < 8; nt++)
                    mma_tf32(acc[mt][nt], a[mt], b[nt]);
        }

        #pragma unroll
        for (int mt = 0; mt < 2; mt++)
            #pragma unroll
            for (int nt = 0; nt < 8; nt++) {
                prs[mt][0] += __expf(acc[mt][nt][0] * SCALE_)
                            + __expf(acc[mt][nt][1] * SCALE_);
                prs[mt][1] += __expf(acc[mt][nt][2] * SCALE_)
                            + __expf(acc[mt][nt][3] * SCALE_);
            }
        __syncthreads();
    }

    // reduce over qc (lanes 4k..4k+3)
    #pragma unroll
    for (int mt = 0; mt < 2; mt++)
        #pragma unroll
        for (int h = 0; h < 2; h++) {
            prs[mt][h] += __shfl_xor_sync(0xffffffffu, prs[mt][h], 1);
            prs[mt][h] += __shfl_xor_sync(0xffffffffu, prs[mt][h], 2);
        }
    if (qc == 0) {
        #pragma unroll
        for (int mt = 0; mt < 2; mt++) {
            prt[(warp & 1) * 128 + wm + mt * 16 + qr]     = prs[mt][0];
            prt[(warp & 1) * 128 + wm + mt * 16 + qr + 8] = prs[mt][1];
        }
    }
    __syncthreads();
    if (t < 128)
        rowsum[(size_t)z * S_ + row0 + t] = prt[t] + prt[128 + t];
}

// ---------------------------------------------------------------------------
// Pass B: recompute QK^T, exp, normalize with precomputed rowsum, write the
// final attn ONCE, and accumulate ctx = P @ V on the fly.
// Block: 128 q-rows; j-tiles of 64. Q resident; K/V/P tiles in smem.
// ---------------------------------------------------------------------------
__global__ __launch_bounds__(256)
void attn_ctx_kernel(const float* __restrict__ Q, const float* __restrict__ K,
                     const float* __restrict__ V, const float* __restrict__ rowsum,
                     float* __restrict__ attn, float* __restrict__ C) {
    extern __shared__ float sm[];
    float* Qs = sm;                          // [128][68]
    float* Ks = sm + 128 * 68;              // [64][68]
    float* Vs = sm + 128 * 68 + 64 * 68;    // [64][72]
    float* Ps = sm + 128 * 68 + 64 * 68 + 64 * 72;  // [128][68]

    const int z = blockIdx.y;
    const size_t ho = (size_t)(z >> 4) * S_ * D_ + (size_t)(z & 15) * DH_;
    const float* Qg = Q + ho;
    const float* Kg = K + ho;
    const float* Vg = V + ho;
    float* Ob = attn + (size_t)z * S_ * S_;
    float* Cg = C + ho;
    const int t = threadIdx.x;
    const int row0 = blockIdx.x * 128;
    const uint32_t qsb = (uint32_t)__cvta_generic_to_shared(Qs);
    const uint32_t ksb = (uint32_t)__cvta_generic_to_shared(Ks);
    const uint32_t vsb = (uint32_t)__cvta_generic_to_shared(Vs);

    // Q tile
    #pragma unroll
    for (int i = 0; i < 8; i++) {
        int idx = t + i * 256;
        int m = idx >> 4, c = idx & 15;
        cpa16(qsb + (uint32_t)((m * 68 + c * 4) * 4),
              Qg + (size_t)(row0 + m) * D_ + c * 4);
    }

    const int lane = t & 31, warp = t >> 5;
    const int wm = (warp >> 1) * 32;
    const int wq = (warp & 1) * 32;    // j-offset (QK^T) / d-offset (PV)
    const int qr = lane >> 2, qc = lane & 3;

    // inverse rowsums for this thread's 4 rows
    float inv[2][2];
    #pragma unroll
    for (int mt = 0; mt < 2; mt++) {
        inv[mt][0] = 1.0f / rowsum[(size_t)z * S_ + row0 + wm + mt * 16 + qr];
        inv[mt][1] = 1.0f / rowsum[(size_t)z * S_ + row0 + wm + mt * 16 + qr + 8];
    }

    float ctx[2][4][4] = {};

    for (int jt = 0; jt < 16; jt++) {
        const int j0 = jt * 64;
        // K tile 64x64, V tile 64x64
        #pragma unroll
        for (int i = 0; i < 4; i++) {
            int idx = t + i * 256;
            int n = idx >> 4, c = idx & 15;
            cpa16(ksb + (uint32_t)((n * 68 + c * 4) * 4),
                  Kg + (size_t)(j0 + n) * D_ + c * 4);
            cpa16(vsb + (uint32_t)((n * 72 + c * 4) * 4),
                  Vg + (size_t)(j0 + n) * D_ + c * 4);
        }
        cp_commit();
        cp_wait0();
        __syncthreads();

        // QK^T: warp tile 32m x 32j
        float p[2][4][4] = {};
        #pragma unroll
        for (int ks = 0; ks < 8; ks++) {
            const int kb = ks * 8;
            float a[2][4], b[4][2];
            #pragma unroll
            for (int mt = 0; mt < 2; mt++) {
                const float* ap = Qs + (wm + mt * 16 + qr) * 68 + kb + qc;
                a[mt][0] = ap[0];       a[mt][1] = ap[8 * 68];
                a[mt][2] = ap[4];       a[mt][3] = ap[8 * 68 + 4];
            }
            #pragma unroll
            for (int nt = 0; nt < 4; nt++) {
                const float* bp = Ks + (wq + nt * 8 + qr) * 68 + kb + qc;
                b[nt][0] = bp[0];       b[nt][1] = bp[4];
            }
            #pragma unroll
            for (int mt = 0; mt < 2; mt++)
                #pragma unroll
                for (int nt = 0; nt < 4; nt++)
                    mma_tf32(p[mt][nt], a[mt], b[nt]);
        }

        // exp, normalize, write attn, stage tf32 P into smem
        #pragma unroll
        for (int mt = 0; mt < 2; mt++) {
            const int rl = wm + mt * 16 + qr;
            #pragma unroll
            for (int nt = 0; nt < 4; nt++) {
                const int cl = wq + nt * 8 + 2 * qc;
                float e0 = __expf(p[mt][nt][0] * SCALE_) * inv[mt][0];
                float e1 = __expf(p[mt][nt][1] * SCALE_) * inv[mt][0];
                float e2 = __expf(p[mt][nt][2] * SCALE_) * inv[mt][1];
                float e3 = __expf(p[mt][nt][3] * SCALE_) * inv[mt][1];
                *(float2*)(Ob + (size_t)(row0 + rl) * S_ + j0 + cl)     = make_float2(e0, e1);
                *(float2*)(Ob + (size_t)(row0 + rl + 8) * S_ + j0 + cl) = make_float2(e2, e3);
                Ps[rl * 68 + cl]           = to_tf32(e0);
                Ps[rl * 68 + cl + 1]       = to_tf32(e1);
                Ps[(rl + 8) * 68 + cl]     = to_tf32(e2);
                Ps[(rl + 8) * 68 + cl + 1] = to_tf32(e3);
            }
        }
        __syncthreads();   // P complete across warps

        // PV: warp tile 32m x 32d, k = 64 (j)
        #pragma unroll
        for (int ks = 0; ks < 8; ks++) {
            const int kb = ks * 8;
            float a[2][4], b[4][2];
            #pragma unroll
            for (int mt = 0; mt < 2; mt++) {
                const float* ap = Ps + (wm + mt * 16 + qr) * 68 + kb + qc;
                a[mt][0] = ap[0];       a[mt][1] = ap[8 * 68];
                a[mt][2] = ap[4];       a[mt][3] = ap[8 * 68 + 4];
            }
            #pragma unroll
            for (int nt = 0; nt < 4; nt++) {
                const float* bp = Vs + (kb + qc) * 72 + wq + nt * 8 + qr;
                b[nt][0] = bp[0];       b[nt][1] = bp[4 * 72];
            }
            #pragma unroll
            for (int mt = 0; mt < 2; mt++)
                #pragma unroll
                for (int nt = 0; nt < 4; nt++)
                    mma_tf32(ctx[mt][nt], a[mt], b[nt]);
        }
        __syncthreads();   // before next tile overwrites Ks/Vs/Ps
    }

    // write ctx (tf32-rounded for O projection)
    #pragma unroll
    for (int mt = 0; mt < 2; mt++) {
        #pragma unroll
        for (int nt = 0; nt < 4; nt++) {
            const int r = row0 + wm + mt * 16 + qr;
            const int c = wq + nt * 8 + 2 * qc;
            float v0 = to_tf32(ctx[mt][nt][0]), v1 = to_tf32(ctx[mt][nt][1]);
            float v2 = to_tf32(ctx[mt][nt][2]), v3 = to_tf32(ctx[mt][nt][3]);
            *(float2*)(Cg + (size_t)r * D_ + c)       = make_float2(v0, v1);
            *(float2*)(Cg + (size_t)(r + 8) * D_ + c) = make_float2(v2, v3);
        }
    }
}

// ---------------------------------------------------------------------------
// Launch
// ---------------------------------------------------------------------------
extern "C" void kernel_launch(void* const* d_in, const int* in_sizes, int n_in,
                              void* d_out, int out_size) {
    const float* query = (const float*)d_in[0];
    const float* key   = (const float*)d_in[1];
    const float* value = (const float*)d_in[2];
    const float* Wq    = (const float*)d_in[3];
    const float* bq    = (const float*)d_in[4];
    const float* Wk    = (const float*)d_in[5];
    const float* bk    = (const float*)d_in[6];
    const float* Wv    = (const float*)d_in[7];
    const float* bv    = (const float*)d_in[8];
    const float* Wo    = (const float*)d_in[9];
    const float* bo    = (const float*)d_in[10];
    float* out = (float*)d_out;

    float *q_ptr, *k_ptr, *v_ptr, *ctx_ptr, *tx_ptr, *tw_ptr, *rs_ptr, *fb_ptr;
    cudaGetSymbolAddress((void**)&q_ptr,   g_q);
    cudaGetSymbolAddress((void**)&k_ptr,   g_k);
    cudaGetSymbolAddress((void**)&v_ptr,   g_v);
    cudaGetSymbolAddress((void**)&ctx_ptr, g_ctx);
    cudaGetSymbolAddress((void**)&tx_ptr,  g_tx);
    cudaGetSymbolAddress((void**)&tw_ptr,  g_tw);
    cudaGetSymbolAddress((void**)&rs_ptr,  g_rowsum);
    cudaGetSymbolAddress((void**)&fb_ptr,  g_attn_fb);

    const long long bhss = (long long)B_ * H_ * S_ * S_;
    float* attn_out = fb_ptr;
    if ((long long)out_size >= (long long)BSD_ + bhss)
        attn_out = out + BSD_;

    const int proj_smem = (2 * PA_ST + 2 * PB_ST) * 4;                       // 71680
    const int rs_smem   = (2 * 128 * 68 + 256) * 4;                          // 70656
    const int ac_smem   = (128 * 68 + 64 * 68 + 64 * 72 + 128 * 68) * 4;     // 105472
    cudaFuncSetAttribute(proj_gemm<true>,  cudaFuncAttributeMaxDynamicSharedMemorySize, proj_smem);
    cudaFuncSetAttribute(proj_gemm<false>, cudaFuncAttributeMaxDynamicSharedMemorySize, proj_smem);
    cudaFuncSetAttribute(rowsum_kernel,    cudaFuncAttributeMaxDynamicSharedMemorySize, rs_smem);
    cudaFuncSetAttribute(attn_ctx_kernel,  cudaFuncAttributeMaxDynamicSharedMemorySize, ac_smem);

    const int n4x = BSD_ / 4, n4w = (D_ * D_) / 4;
    dim3 gproj(D_ / 128, (B_ * S_) / 128);

    cvt_rna_kernel<<<(n4x + 255) / 256, 256>>>((const float4*)query, (float4*)tx_ptr, n4x);
    cvt_rna_kernel<<<(n4w + 255) / 256, 256>>>((const float4*)Wq, (float4*)tw_ptr, n4w);
    proj_gemm<true><<<gproj, 256, proj_smem>>>(tx_ptr, tw_ptr, bq, q_ptr);

    cvt_rna_kernel<<<(n4x + 255) / 256, 256>>>((const float4*)key, (float4*)tx_ptr, n4x);
    cvt_rna_kernel<<<(n4w + 255) / 256, 256>>>((const float4*)Wk, (float4*)tw_ptr, n4w);
    proj_gemm<true><<<gproj, 256, proj_smem>>>(tx_ptr, tw_ptr, bk, k_ptr);

    cvt_rna_kernel<<<(n4x + 255) / 256, 256>>>((const float4*)value, (float4*)tx_ptr, n4x);
    cvt_rna_kernel<<<(n4w + 255) / 256, 256>>>((const float4*)Wv, (float4*)tw_ptr, n4w);
    proj_gemm<true><<<gproj, 256, proj_smem>>>(tx_ptr, tw_ptr, bv, v_ptr);

    dim3 gattn(S_ / 128, B_ * H_);   // (8, 128)
    rowsum_kernel<<<gattn, 256, rs_smem>>>(q_ptr, k_ptr, rs_ptr);
    attn_ctx_kernel<<<gattn, 256, ac_smem>>>(q_ptr, k_ptr, v_ptr, rs_ptr, attn_out, ctx_ptr);

    cvt_rna_kernel<<<(n4w + 255) / 256, 256>>>((const float4*)Wo, (float4*)tw_ptr, n4w);
    proj_gemm<false><<<gproj, 256, proj_smem>>>(ctx_ptr, tw_ptr, bo, out);
}